// round 6
// baseline (speedup 1.0000x reference)
#include <cuda_runtime.h>

#define NBATCH 256
#define NTIME  256
#define NS     512   // state size
#define NE     128   // embedding
#define NALPH  128   // alphabet / output
#define FAN    640   // NE + NS
#define BT     (NBATCH * NTIME)

typedef unsigned long long u64;

// ---- scratch (static __device__: allocation-free per harness rules) ----
__device__ float g_fin[BT * NS];        // fin[(b*NTIME+t)*NS + n]
__device__ float g_states[BT * NS];     // states[(b*NTIME+t)*NS + n] (also the recurrent state)
__device__ int   g_bar[NTIME];          // per-step grid barrier counters

// ---- packed fp32x2 helpers (Blackwell FFMA2) ----
__device__ __forceinline__ void fma2(u64& d, u64 a, u64 b) {
    asm("fma.rn.f32x2 %0, %1, %2, %0;" : "+l"(d) : "l"(a), "l"(b));
}
__device__ __forceinline__ float hadd2(u64 v) {
    float lo, hi;
    asm("mov.b64 {%0,%1}, %2;" : "=f"(lo), "=f"(hi) : "l"(v));
    return lo + hi;
}

// =====================================================================
// reset: zero barrier counters (fresh per launch -> graph-replay safe)
// =====================================================================
__global__ void reset_kernel() {
    int i = threadIdx.x;
    if (i < NTIME) g_bar[i] = 0;
}

// =====================================================================
// Phase 1: fin[bt][n] = dot(emb[w[bt]], W_in[n][0:128]) + b_in[n]
// grid (BT/64, NS/64), block 256, 64x64 tile, 4x4 micro (scalar fp32)
// =====================================================================
__global__ void __launch_bounds__(256)
fin_kernel(const int* __restrict__ w,
           const float* __restrict__ emb,
           const float* __restrict__ W_in,
           const float* __restrict__ b_in) {
    __shared__ int   widx[64];
    __shared__ float As[64 * 36];
    __shared__ float Bs[64 * 33];

    int tid = threadIdx.x;
    int tx = tid & 15, ty = tid >> 4;
    int bt0 = blockIdx.x * 64;
    int n0  = blockIdx.y * 64;

    if (tid < 64) widx[tid] = w[bt0 + tid];
    __syncthreads();

    float acc[4][4] = {};

    for (int kc = 0; kc < NE; kc += 32) {
        for (int s = tid; s < 512; s += 256) {
            int row = s >> 3, q = (s & 7) << 2;
            float4 v = *(const float4*)&emb[widx[row] * NE + kc + q];
            *(float4*)&As[row * 36 + q] = v;
        }
        for (int s = tid; s < 512; s += 256) {
            int row = s >> 3, q = (s & 7) << 2;
            float4 v = *(const float4*)&W_in[(n0 + row) * FAN + kc + q];
            float* d = &Bs[row * 33 + q];
            d[0] = v.x; d[1] = v.y; d[2] = v.z; d[3] = v.w;
        }
        __syncthreads();
        #pragma unroll
        for (int k = 0; k < 32; ++k) {
            float a[4], b[4];
            #pragma unroll
            for (int i = 0; i < 4; ++i) a[i] = As[(ty + 16 * i) * 36 + k];
            #pragma unroll
            for (int j = 0; j < 4; ++j) b[j] = Bs[(tx + 16 * j) * 33 + k];
            #pragma unroll
            for (int i = 0; i < 4; ++i)
                #pragma unroll
                for (int j = 0; j < 4; ++j)
                    acc[i][j] = fmaf(a[i], b[j], acc[i][j]);
        }
        __syncthreads();
    }

    #pragma unroll
    for (int i = 0; i < 4; ++i) {
        int r = bt0 + ty + 16 * i;
        #pragma unroll
        for (int j = 0; j < 4; ++j) {
            int c = n0 + tx + 16 * j;
            g_fin[r * NS + c] = acc[i][j] + b_in[c];
        }
    }
}

// =====================================================================
// Phase 2: persistent recurrent kernel.
// grid = 128 blocks (16 row-tiles of 16 batch rows x 8 col-tiles of 64
// state cols). Block = 256 threads (8 warps, 2/SMSP for latency hiding).
// Warp w exclusively owns cols [8w, 8w+8) of the tile -> B smem rows are
// NOT re-read by other warps (2.8x less crossbar traffic than R5).
// Thread micro-tile: 4 rows x 1 col, packed f32x2 accumulators.
// =====================================================================
__global__ void __launch_bounds__(256, 1)
rnn_kernel(const float* __restrict__ W_in) {
    extern __shared__ float sm[];
    float* Bs = sm;                 // [64][516]  W_s slice
    float* As = sm + 64 * 516;      // [16][520]  state tile

    const int tid  = threadIdx.x;
    const int wrp  = tid >> 5;      // 0..7
    const int lane = tid & 31;
    const int tx   = lane & 7;      // 0..7  (col within warp's 8-col strip)
    const int tyq  = lane >> 3;     // 0..3  (row quadrant)
    const int rb0 = (blockIdx.x & 15) * 16;
    const int cb0 = (blockIdx.x >> 4) * 64;

    // Load W_s slice once: Bs[n][k] = W_in[(cb0+n)*FAN + NE + k]
    for (int s = tid; s < 64 * 128; s += 256) {
        int row = s >> 7, q = (s & 127) << 2;
        float4 v = *(const float4*)&W_in[(cb0 + row) * FAN + NE + q];
        *(float4*)&Bs[row * 516 + q] = v;
    }
    __syncthreads();

    const int mycol = 8 * wrp + tx;             // 0..63 within tile
    const float* bp  = Bs + mycol * 516;
    const float* ap0 = As + (tyq)      * 520;
    const float* ap1 = As + (tyq + 4)  * 520;
    const float* ap2 = As + (tyq + 8)  * 520;
    const float* ap3 = As + (tyq + 12) * 520;

    const int c  = cb0 + mycol;                 // global state col
    int rr[4];
    rr[0] = rb0 + tyq; rr[1] = rb0 + tyq + 4;
    rr[2] = rb0 + tyq + 8; rr[3] = rb0 + tyq + 12;

    // prefetch fin for t = 0
    float ffin[4];
    #pragma unroll
    for (int i = 0; i < 4; ++i)
        ffin[i] = __ldcg(&g_fin[(rr[i] * NTIME + 0) * NS + c]);

    for (int t = 0; t < NTIME; ++t) {
        u64 acc[4] = {};

        if (t > 0) {
            #pragma unroll 4
            for (int k = 0; k < NS; k += 4) {
                ulonglong2 B  = *(const ulonglong2*)(bp  + k);
                ulonglong2 A0 = *(const ulonglong2*)(ap0 + k);
                ulonglong2 A1 = *(const ulonglong2*)(ap1 + k);
                ulonglong2 A2 = *(const ulonglong2*)(ap2 + k);
                ulonglong2 A3 = *(const ulonglong2*)(ap3 + k);
                fma2(acc[0], A0.x, B.x); fma2(acc[0], A0.y, B.y);
                fma2(acc[1], A1.x, B.x); fma2(acc[1], A1.y, B.y);
                fma2(acc[2], A2.x, B.x); fma2(acc[2], A2.y, B.y);
                fma2(acc[3], A3.x, B.x); fma2(acc[3], A3.y, B.y);
            }
        }

        // epilogue: tanh(acc + fin_t) -> states log (this IS the state)
        #pragma unroll
        for (int i = 0; i < 4; ++i) {
            float v = tanhf(hadd2(acc[i]) + ffin[i]);
            g_states[(rr[i] * NTIME + t) * NS + c] = v;
        }
        __syncthreads();          // all state STGs issued, As reads done

        if (t + 1 < NTIME) {
            if (tid == 0) {
                __threadfence();                 // release this tile's writes
                atomicAdd(&g_bar[t], 1);         // arrive
            }
            // -- prefetch fin(t+1), overlapped with other blocks' arrival --
            #pragma unroll
            for (int i = 0; i < 4; ++i)
                ffin[i] = __ldcg(&g_fin[(rr[i] * NTIME + t + 1) * NS + c]);
            if (tid == 0) {
                while (*((volatile int*)&g_bar[t]) < 128) { }
            }
            __syncthreads();

            // stage states[t] (written by all blocks) for step t+1
            #pragma unroll
            for (int s = tid; s < 16 * 128; s += 256) {
                int row = s >> 7, q4 = (s & 127) << 2;
                float4 v = __ldcg((const float4*)
                    &g_states[((rb0 + row) * NTIME + t) * NS + q4]);
                *(float4*)&As[row * 520 + q4] = v;
            }
            __syncthreads();
        }
    }
}

// =====================================================================
// Phase 3: y[bt][a] = dot(states[bt], W_out[a]) + b_out[a]
// grid (BT/64, NALPH/64), block 256, 64x64 tile, 4x4 micro (scalar fp32)
// =====================================================================
__global__ void __launch_bounds__(256)
out_kernel(const float* __restrict__ W_out,
           const float* __restrict__ b_out,
           float* __restrict__ y) {
    __shared__ float As[64 * 36];
    __shared__ float Bs[64 * 33];

    int tid = threadIdx.x;
    int tx = tid & 15, ty = tid >> 4;
    int bt0 = blockIdx.x * 64;
    int a0  = blockIdx.y * 64;

    float acc[4][4] = {};

    for (int kc = 0; kc < NS; kc += 32) {
        for (int s = tid; s < 512; s += 256) {
            int row = s >> 3, q = (s & 7) << 2;
            float4 v = *(const float4*)&g_states[(bt0 + row) * NS + kc + q];
            *(float4*)&As[row * 36 + q] = v;
        }
        for (int s = tid; s < 512; s += 256) {
            int row = s >> 3, q = (s & 7) << 2;
            float4 v = *(const float4*)&W_out[(a0 + row) * NS + kc + q];
            float* d = &Bs[row * 33 + q];
            d[0] = v.x; d[1] = v.y; d[2] = v.z; d[3] = v.w;
        }
        __syncthreads();
        #pragma unroll
        for (int k = 0; k < 32; ++k) {
            float a[4], b[4];
            #pragma unroll
            for (int i = 0; i < 4; ++i) a[i] = As[(ty + 16 * i) * 36 + k];
            #pragma unroll
            for (int j = 0; j < 4; ++j) b[j] = Bs[(tx + 16 * j) * 33 + k];
            #pragma unroll
            for (int i = 0; i < 4; ++i)
                #pragma unroll
                for (int j = 0; j < 4; ++j)
                    acc[i][j] = fmaf(a[i], b[j], acc[i][j]);
        }
        __syncthreads();
    }

    #pragma unroll
    for (int i = 0; i < 4; ++i) {
        int r = bt0 + ty + 16 * i;
        #pragma unroll
        for (int j = 0; j < 4; ++j) {
            int c = a0 + tx + 16 * j;
            y[r * NALPH + c] = acc[i][j] + b_out[c];
        }
    }
}

// =====================================================================
// launch
// =====================================================================
extern "C" void kernel_launch(void* const* d_in, const int* in_sizes, int n_in,
                              void* d_out, int out_size) {
    const int*   w     = (const int*)  d_in[0];
    const float* emb   = (const float*)d_in[1];
    const float* W_in  = (const float*)d_in[2];
    const float* b_in  = (const float*)d_in[3];
    const float* W_out = (const float*)d_in[4];
    const float* b_out = (const float*)d_in[5];
    float* y = (float*)d_out;

    // persistent kernel needs ~165 KB dynamic smem (opt-in above 48 KB)
    size_t rnn_smem = (size_t)(64 * 516 + 16 * 520) * sizeof(float);
    cudaFuncSetAttribute(rnn_kernel,
                         cudaFuncAttributeMaxDynamicSharedMemorySize,
                         (int)rnn_smem);

    reset_kernel<<<1, 256>>>();
    fin_kernel<<<dim3(BT / 64, NS / 64), 256>>>(w, emb, W_in, b_in);
    rnn_kernel<<<128, 256, rnn_smem>>>(W_in);
    out_kernel<<<dim3(BT / 64, NALPH / 64), 256>>>(W_out, b_out, y);
}

// round 7
// speedup vs baseline: 1.0205x; 1.0205x over previous
#include <cuda_runtime.h>

#define NBATCH 256
#define NTIME  256
#define NS     512   // state size
#define NE     128   // embedding
#define NALPH  128   // alphabet / output
#define FAN    640   // NE + NS
#define BT     (NBATCH * NTIME)

#define NROWT  16    // row tiles (16 batch rows each)
#define NCOLT  8     // col tiles (64 state cols each)

typedef unsigned long long u64;

// ---- scratch (static __device__: allocation-free per harness rules) ----
__device__ float g_fin[BT * NS];          // fin[(b*NTIME+t)*NS + n]
__device__ float g_states[BT * NS];       // states[(b*NTIME+t)*NS + n] (also the recurrent state)
__device__ int   g_bar[NTIME * NROWT];    // per-(step,rowtile) barrier counters

// ---- packed fp32x2 helpers (Blackwell FFMA2) ----
__device__ __forceinline__ void fma2(u64& d, u64 a, u64 b) {
    asm("fma.rn.f32x2 %0, %1, %2, %0;" : "+l"(d) : "l"(a), "l"(b));
}
__device__ __forceinline__ float hadd2(u64 v) {
    float lo, hi;
    asm("mov.b64 {%0,%1}, %2;" : "=f"(lo), "=f"(hi) : "l"(v));
    return lo + hi;
}

// =====================================================================
// reset: zero barrier counters (fresh per launch -> graph-replay safe)
// =====================================================================
__global__ void reset_kernel() {
    int i = blockIdx.x * blockDim.x + threadIdx.x;
    if (i < NTIME * NROWT) g_bar[i] = 0;
}

// =====================================================================
// Phase 1: fin[bt][n] = dot(emb[w[bt]], W_in[n][0:128]) + b_in[n]
// grid (BT/64, NS/64), block 256, 64x64 tile, 4x4 micro (scalar fp32)
// =====================================================================
__global__ void __launch_bounds__(256)
fin_kernel(const int* __restrict__ w,
           const float* __restrict__ emb,
           const float* __restrict__ W_in,
           const float* __restrict__ b_in) {
    __shared__ int   widx[64];
    __shared__ float As[64 * 36];
    __shared__ float Bs[64 * 33];

    int tid = threadIdx.x;
    int tx = tid & 15, ty = tid >> 4;
    int bt0 = blockIdx.x * 64;
    int n0  = blockIdx.y * 64;

    if (tid < 64) widx[tid] = w[bt0 + tid];
    __syncthreads();

    float acc[4][4] = {};

    for (int kc = 0; kc < NE; kc += 32) {
        for (int s = tid; s < 512; s += 256) {
            int row = s >> 3, q = (s & 7) << 2;
            float4 v = *(const float4*)&emb[widx[row] * NE + kc + q];
            *(float4*)&As[row * 36 + q] = v;
        }
        for (int s = tid; s < 512; s += 256) {
            int row = s >> 3, q = (s & 7) << 2;
            float4 v = *(const float4*)&W_in[(n0 + row) * FAN + kc + q];
            float* d = &Bs[row * 33 + q];
            d[0] = v.x; d[1] = v.y; d[2] = v.z; d[3] = v.w;
        }
        __syncthreads();
        #pragma unroll
        for (int k = 0; k < 32; ++k) {
            float a[4], b[4];
            #pragma unroll
            for (int i = 0; i < 4; ++i) a[i] = As[(ty + 16 * i) * 36 + k];
            #pragma unroll
            for (int j = 0; j < 4; ++j) b[j] = Bs[(tx + 16 * j) * 33 + k];
            #pragma unroll
            for (int i = 0; i < 4; ++i)
                #pragma unroll
                for (int j = 0; j < 4; ++j)
                    acc[i][j] = fmaf(a[i], b[j], acc[i][j]);
        }
        __syncthreads();
    }

    #pragma unroll
    for (int i = 0; i < 4; ++i) {
        int r = bt0 + ty + 16 * i;
        #pragma unroll
        for (int j = 0; j < 4; ++j) {
            int c = n0 + tx + 16 * j;
            g_fin[r * NS + c] = acc[i][j] + b_in[c];
        }
    }
}

// =====================================================================
// Phase 2: persistent recurrent kernel.
// grid = 128 blocks: rowtile = bid>>3 (16 batch rows), coltile = bid&7
// (64 state cols). Block = 256 threads, warp w owns cols [8w,8w+8).
// SYNC IS PER-ROWTILE: batch rows are independent, so block (r,c) only
// waits for the 8 blocks sharing rowtile r. The 16 groups pipeline
// independently -- no chip-wide straggler serialization.
// =====================================================================
__global__ void __launch_bounds__(256, 1)
rnn_kernel(const float* __restrict__ W_in) {
    extern __shared__ float sm[];
    float* Bs = sm;                 // [64][516]  W_s slice
    float* As = sm + 64 * 516;      // [16][520]  state tile

    const int tid  = threadIdx.x;
    const int wrp  = tid >> 5;      // 0..7
    const int lane = tid & 31;
    const int tx   = lane & 7;      // 0..7  (col within warp's 8-col strip)
    const int tyq  = lane >> 3;     // 0..3  (row quadrant)
    const int rowtile = blockIdx.x >> 3;   // 0..15
    const int coltile = blockIdx.x & 7;    // 0..7
    const int rb0 = rowtile * 16;
    const int cb0 = coltile * 64;

    // Load W_s slice once: Bs[n][k] = W_in[(cb0+n)*FAN + NE + k]
    for (int s = tid; s < 64 * 128; s += 256) {
        int row = s >> 7, q = (s & 127) << 2;
        float4 v = *(const float4*)&W_in[(cb0 + row) * FAN + NE + q];
        *(float4*)&Bs[row * 516 + q] = v;
    }
    __syncthreads();

    const int mycol = 8 * wrp + tx;             // 0..63 within tile
    const float* bp  = Bs + mycol * 516;
    const float* ap0 = As + (tyq)      * 520;
    const float* ap1 = As + (tyq + 4)  * 520;
    const float* ap2 = As + (tyq + 8)  * 520;
    const float* ap3 = As + (tyq + 12) * 520;

    const int c  = cb0 + mycol;                 // global state col
    int rr[4];
    rr[0] = rb0 + tyq; rr[1] = rb0 + tyq + 4;
    rr[2] = rb0 + tyq + 8; rr[3] = rb0 + tyq + 12;

    // prefetch fin for t = 0
    float ffin[4];
    #pragma unroll
    for (int i = 0; i < 4; ++i)
        ffin[i] = __ldcg(&g_fin[(rr[i] * NTIME + 0) * NS + c]);

    for (int t = 0; t < NTIME; ++t) {
        u64 acc[4] = {};

        if (t > 0) {
            #pragma unroll 4
            for (int k = 0; k < NS; k += 4) {
                ulonglong2 B  = *(const ulonglong2*)(bp  + k);
                ulonglong2 A0 = *(const ulonglong2*)(ap0 + k);
                ulonglong2 A1 = *(const ulonglong2*)(ap1 + k);
                ulonglong2 A2 = *(const ulonglong2*)(ap2 + k);
                ulonglong2 A3 = *(const ulonglong2*)(ap3 + k);
                fma2(acc[0], A0.x, B.x); fma2(acc[0], A0.y, B.y);
                fma2(acc[1], A1.x, B.x); fma2(acc[1], A1.y, B.y);
                fma2(acc[2], A2.x, B.x); fma2(acc[2], A2.y, B.y);
                fma2(acc[3], A3.x, B.x); fma2(acc[3], A3.y, B.y);
            }
        }

        // epilogue: tanh(acc + fin_t) -> states log (this IS the state)
        #pragma unroll
        for (int i = 0; i < 4; ++i) {
            float v = tanhf(hadd2(acc[i]) + ffin[i]);
            g_states[(rr[i] * NTIME + t) * NS + c] = v;
        }
        __syncthreads();          // all state STGs issued, As reads done

        if (t + 1 < NTIME) {
            int* bar = &g_bar[t * NROWT + rowtile];
            if (tid == 0) {
                __threadfence();                 // release this strip's writes
                atomicAdd(bar, 1);               // arrive (group of 8)
            }
            // -- prefetch fin(t+1), overlapped with peers' arrival --
            #pragma unroll
            for (int i = 0; i < 4; ++i)
                ffin[i] = __ldcg(&g_fin[(rr[i] * NTIME + t + 1) * NS + c]);
            if (tid == 0) {
                while (*((volatile int*)bar) < NCOLT) { }
            }
            __syncthreads();

            // stage states[t] for this rowtile (written by the 8 group blocks)
            #pragma unroll
            for (int s = tid; s < 16 * 128; s += 256) {
                int row = s >> 7, q4 = (s & 127) << 2;
                float4 v = __ldcg((const float4*)
                    &g_states[((rb0 + row) * NTIME + t) * NS + q4]);
                *(float4*)&As[row * 520 + q4] = v;
            }
            __syncthreads();
        }
    }
}

// =====================================================================
// Phase 3: y[bt][a] = dot(states[bt], W_out[a]) + b_out[a]
// grid (BT/64, NALPH/64), block 256, 64x64 tile, 4x4 micro (scalar fp32)
// =====================================================================
__global__ void __launch_bounds__(256)
out_kernel(const float* __restrict__ W_out,
           const float* __restrict__ b_out,
           float* __restrict__ y) {
    __shared__ float As[64 * 36];
    __shared__ float Bs[64 * 33];

    int tid = threadIdx.x;
    int tx = tid & 15, ty = tid >> 4;
    int bt0 = blockIdx.x * 64;
    int a0  = blockIdx.y * 64;

    float acc[4][4] = {};

    for (int kc = 0; kc < NS; kc += 32) {
        for (int s = tid; s < 512; s += 256) {
            int row = s >> 3, q = (s & 7) << 2;
            float4 v = *(const float4*)&g_states[(bt0 + row) * NS + kc + q];
            *(float4*)&As[row * 36 + q] = v;
        }
        for (int s = tid; s < 512; s += 256) {
            int row = s >> 3, q = (s & 7) << 2;
            float4 v = *(const float4*)&W_out[(a0 + row) * NS + kc + q];
            float* d = &Bs[row * 33 + q];
            d[0] = v.x; d[1] = v.y; d[2] = v.z; d[3] = v.w;
        }
        __syncthreads();
        #pragma unroll
        for (int k = 0; k < 32; ++k) {
            float a[4], b[4];
            #pragma unroll
            for (int i = 0; i < 4; ++i) a[i] = As[(ty + 16 * i) * 36 + k];
            #pragma unroll
            for (int j = 0; j < 4; ++j) b[j] = Bs[(tx + 16 * j) * 33 + k];
            #pragma unroll
            for (int i = 0; i < 4; ++i)
                #pragma unroll
                for (int j = 0; j < 4; ++j)
                    acc[i][j] = fmaf(a[i], b[j], acc[i][j]);
        }
        __syncthreads();
    }

    #pragma unroll
    for (int i = 0; i < 4; ++i) {
        int r = bt0 + ty + 16 * i;
        #pragma unroll
        for (int j = 0; j < 4; ++j) {
            int c = a0 + tx + 16 * j;
            y[r * NALPH + c] = acc[i][j] + b_out[c];
        }
    }
}

// =====================================================================
// launch
// =====================================================================
extern "C" void kernel_launch(void* const* d_in, const int* in_sizes, int n_in,
                              void* d_out, int out_size) {
    const int*   w     = (const int*)  d_in[0];
    const float* emb   = (const float*)d_in[1];
    const float* W_in  = (const float*)d_in[2];
    const float* b_in  = (const float*)d_in[3];
    const float* W_out = (const float*)d_in[4];
    const float* b_out = (const float*)d_in[5];
    float* y = (float*)d_out;

    // persistent kernel needs ~165 KB dynamic smem (opt-in above 48 KB)
    size_t rnn_smem = (size_t)(64 * 516 + 16 * 520) * sizeof(float);
    cudaFuncSetAttribute(rnn_kernel,
                         cudaFuncAttributeMaxDynamicSharedMemorySize,
                         (int)rnn_smem);

    reset_kernel<<<(NTIME * NROWT + 255) / 256, 256>>>();
    fin_kernel<<<dim3(BT / 64, NS / 64), 256>>>(w, emb, W_in, b_in);
    rnn_kernel<<<128, 256, rnn_smem>>>(W_in);
    out_kernel<<<dim3(BT / 64, NALPH / 64), 256>>>(W_out, b_out, y);
}